// round 10
// baseline (speedup 1.0000x reference)
#include <cuda_runtime.h>
#include <cuda_bf16.h>
#include <math.h>
#include <string.h>

// support [25,2560] f32, query [4096,2560] f32 -> out [4096,5] f32
#define D       2560
#define NS      25
#define NWAY    5
#define KSHOT   5
#define EPSV    1e-6f

#define MR      32              // query rows per CTA
#define NRB     128             // NQ / MR
#define NSPLIT  2
#define KH      1280            // K per CTA
#define KSUB    64              // f32 cols per stage
#define NSTG    20              // KH / KSUB
#define ST      4               // ring depth
#define RSTR    72              // smem row stride in floats (72 mod 32 == 8: conflict-free)
#define THREADS 128
#define STAGEF  (2 * 32 * RSTR)         // A(32xRSTR) + B(32xRSTR) floats
#define DSMEM   (ST * STAGEF * 4)       // 73728 bytes

typedef unsigned long long u64;

// per-half partials: cols 0..24 dots, 25 qsum (ones row), 26 qn
__device__ float g_part[NSPLIT][NRB][MR][27];
__device__ float g_snh [NSPLIT][NRB][NS];   // per-half support norm term
__device__ int   g_ctr [NRB];               // zero-init; self-resetting

__device__ __forceinline__ u64 ffma2(u64 a, u64 b, u64 c) {
    u64 d;
    asm("fma.rn.f32x2 %0, %1, %2, %3;" : "=l"(d) : "l"(a), "l"(b), "l"(c));
    return d;
}
__device__ __forceinline__ u64 fadd2(u64 a, u64 b) {
    u64 d;
    asm("add.rn.f32x2 %0, %1, %2;" : "=l"(d) : "l"(a), "l"(b));
    return d;
}
__device__ __forceinline__ float f2_sum(u64 v) {
    return __uint_as_float((unsigned)(v & 0xffffffffull)) +
           __uint_as_float((unsigned)(v >> 32));
}
__device__ __forceinline__ u64 as_u64(float2 v) {
    u64 r; memcpy(&r, &v, 8); return r;
}
__device__ __forceinline__ unsigned cvt_bf2(float2 v) {
    __nv_bfloat162 p = __floats2bfloat162_rn(v.x, v.y);
    unsigned r; memcpy(&r, &p, 4); return r;
}
__device__ __forceinline__ void mma16816(float c[4],
                                         unsigned a0, unsigned a1,
                                         unsigned a2, unsigned a3,
                                         unsigned b0, unsigned b1) {
    asm volatile(
        "mma.sync.aligned.m16n8k16.row.col.f32.bf16.bf16.f32 "
        "{%0,%1,%2,%3}, {%4,%5,%6,%7}, {%8,%9}, {%0,%1,%2,%3};"
        : "+f"(c[0]), "+f"(c[1]), "+f"(c[2]), "+f"(c[3])
        : "r"(a0), "r"(a1), "r"(a2), "r"(a3), "r"(b0), "r"(b1));
}

// ---------------------------------------------------------------------------
// CTA = (row block rbc: 32 rows, K-half h). 4 warps split M x N:
//   warp w: mh = w&1 (rows mh*16 + {gid, gid+8}), nh = w>>1 (n-tiles nh*2, nh*2+1)
// Warps own DISJOINT outputs -> results written directly to global, no
// intra-CTA reduction. A (query, f32) and B (support, f32; row 25 = ones,
// 26..31 = zeros) stream through a shared 4-stage cp.async ring; fragments
// built by LDS + in-register f32->bf16 cvt. Support-norm terms accumulated
// from the same B fragment values. 2-way cross-CTA finish via counter.
// ---------------------------------------------------------------------------
__global__ __launch_bounds__(THREADS, 2)
void pd_mma(const float* __restrict__ support,
            const float* __restrict__ query,
            float* __restrict__ out) {
    extern __shared__ float ring[];   // [ST][A 32*RSTR | B 32*RSTR]
    __shared__ float s_sn[NS];
    __shared__ int   s_flag;

    const int tid = threadIdx.x;
    const int w   = tid >> 5;
    const int ln  = tid & 31;
    const int gid = ln >> 2;
    const int tig = ln & 3;
    const int mh  = w & 1;
    const int nh  = w >> 1;
    const int rbc = blockIdx.x;
    const int h   = blockIdx.y;

    const float* qrow0 = query + (size_t)(rbc * MR) * D + h * KH;
    const float* srow0 = support + h * KH;

    // ---- prefill B pad rows for all ring slots: row 25 = ones, 26..31 = 0 ----
    for (int i = tid; i < ST * 7 * RSTR; i += THREADS) {
        const int slot = i / (7 * RSTR);
        const int rem  = i - slot * 7 * RSTR;
        const int row  = 25 + rem / RSTR;
        const int col  = rem % RSTR;
        ring[slot * STAGEF + 32 * RSTR + row * RSTR + col] =
            (row == 25 && col < KSUB) ? 1.f : 0.f;
    }

    // ---- cp.async stage issue: A 32x64, B 25x64 (f32, 16B segs) ----
    auto issue_stage = [&](int st) {
        if (st < NSTG) {
            float* base = ring + (st & (ST - 1)) * STAGEF;
            const int kb = st * KSUB;
            #pragma unroll
            for (int j = 0; j < 4; ++j) {          // A: 512 segs
                const int i   = tid + j * THREADS;
                const int row = i >> 4;
                const int seg = i & 15;
                const float* src = qrow0 + (size_t)row * D + kb + seg * 4;
                const unsigned dst = (unsigned)__cvta_generic_to_shared(
                    base + row * RSTR + seg * 4);
                asm volatile("cp.async.cg.shared.global [%0], [%1], 16;"
                             :: "r"(dst), "l"(src));
            }
            #pragma unroll
            for (int j = 0; j < 4; ++j) {          // B: 400 segs (25 rows)
                const int i = tid + j * THREADS;
                if (i < 400) {
                    const int row = i >> 4;
                    const int seg = i & 15;
                    const float* src = srow0 + (size_t)row * D + kb + seg * 4;
                    const unsigned dst = (unsigned)__cvta_generic_to_shared(
                        base + 32 * RSTR + row * RSTR + seg * 4);
                    asm volatile("cp.async.cg.shared.global [%0], [%1], 16;"
                                 :: "r"(dst), "l"(src));
                }
            }
        }
        asm volatile("cp.async.commit_group;");
    };

    issue_stage(0); issue_stage(1); issue_stage(2);

    // ---- accumulators ----
    float c0[4], c1[4];                 // two n-tiles
    #pragma unroll
    for (int i = 0; i < 4; ++i) { c0[i] = 0.f; c1[i] = 0.f; }
    u64 qn0 = 0ull, qn1 = 0ull;         // rows mh*16+gid, +8 (nh==0 only)
    u64 ssq20 = 0ull, ssm20 = 0ull;     // B row nrow0
    u64 ssq21 = 0ull, ssm21 = 0ull;     // B row nrow1

    const int arow0 = mh * 16 + gid;
    const int nrow0 = (nh * 2)     * 8 + gid;
    const int nrow1 = (nh * 2 + 1) * 8 + gid;

    for (int st = 0; st < NSTG; ++st) {
        asm volatile("cp.async.wait_group 2;");
        __syncthreads();                       // stage st ready for all
        const float* A = ring + (st & (ST - 1)) * STAGEF;
        const float* B = A + 32 * RSTR;
        #pragma unroll
        for (int cc = 0; cc < 4; ++cc) {
            const int k0 = cc * 16 + tig * 2;
            const float2 a0 = *(const float2*)(A + arow0 * RSTR + k0);
            const float2 a1 = *(const float2*)(A + (arow0 + 8) * RSTR + k0);
            const float2 a2 = *(const float2*)(A + arow0 * RSTR + k0 + 8);
            const float2 a3 = *(const float2*)(A + (arow0 + 8) * RSTR + k0 + 8);
            if (nh == 0) {
                qn0 = ffma2(as_u64(a0), as_u64(a0), qn0);
                qn0 = ffma2(as_u64(a2), as_u64(a2), qn0);
                qn1 = ffma2(as_u64(a1), as_u64(a1), qn1);
                qn1 = ffma2(as_u64(a3), as_u64(a3), qn1);
            }
            const unsigned ra0 = cvt_bf2(a0), ra1 = cvt_bf2(a1);
            const unsigned ra2 = cvt_bf2(a2), ra3 = cvt_bf2(a3);

            const float2 b00 = *(const float2*)(B + nrow0 * RSTR + k0);
            const float2 b01 = *(const float2*)(B + nrow0 * RSTR + k0 + 8);
            const float2 b10 = *(const float2*)(B + nrow1 * RSTR + k0);
            const float2 b11 = *(const float2*)(B + nrow1 * RSTR + k0 + 8);
            ssq20 = ffma2(as_u64(b00), as_u64(b00), ssq20);
            ssq20 = ffma2(as_u64(b01), as_u64(b01), ssq20);
            ssm20 = fadd2(ssm20, as_u64(b00));
            ssm20 = fadd2(ssm20, as_u64(b01));
            ssq21 = ffma2(as_u64(b10), as_u64(b10), ssq21);
            ssq21 = ffma2(as_u64(b11), as_u64(b11), ssq21);
            ssm21 = fadd2(ssm21, as_u64(b10));
            ssm21 = fadd2(ssm21, as_u64(b11));

            mma16816(c0, ra0, ra1, ra2, ra3, cvt_bf2(b00), cvt_bf2(b01));
            mma16816(c1, ra0, ra1, ra2, ra3, cvt_bf2(b10), cvt_bf2(b11));
        }
        // slot (st+3)&3 == slot (st-1): consumed last iteration, freed by
        // this iteration's barrier -> safe to overwrite, no second barrier.
        issue_stage(st + 3);
    }

    // ---- reduce over tig lanes (xor 1,2 stay in quad) and publish ----
    if (nh == 0) {
        float q0 = f2_sum(qn0), q1 = f2_sum(qn1);
        q0 += __shfl_xor_sync(0xffffffffu, q0, 1);
        q0 += __shfl_xor_sync(0xffffffffu, q0, 2);
        q1 += __shfl_xor_sync(0xffffffffu, q1, 1);
        q1 += __shfl_xor_sync(0xffffffffu, q1, 2);
        if (tig == 0) {
            g_part[h][rbc][arow0][26]     = q0;
            g_part[h][rbc][arow0 + 8][26] = q1;
        }
    }
    {
        float s0 = f2_sum(ssq20), m0 = f2_sum(ssm20);
        float s1 = f2_sum(ssq21), m1 = f2_sum(ssm21);
        s0 += __shfl_xor_sync(0xffffffffu, s0, 1);
        s0 += __shfl_xor_sync(0xffffffffu, s0, 2);
        m0 += __shfl_xor_sync(0xffffffffu, m0, 1);
        m0 += __shfl_xor_sync(0xffffffffu, m0, 2);
        s1 += __shfl_xor_sync(0xffffffffu, s1, 1);
        s1 += __shfl_xor_sync(0xffffffffu, s1, 2);
        m1 += __shfl_xor_sync(0xffffffffu, m1, 1);
        m1 += __shfl_xor_sync(0xffffffffu, m1, 2);
        if (tig == 0 && mh == 0) {   // one writer per B row
            if (nrow0 < NS) g_snh[h][rbc][nrow0] = s0 + 2.f * EPSV * m0;
            if (nrow1 < NS) g_snh[h][rbc][nrow1] = s1 + 2.f * EPSV * m1;
        }
    }
    // dots (+ qsum at col 25): disjoint (row,col) per lane -> direct stores
    #pragma unroll
    for (int ntl = 0; ntl < 2; ++ntl) {
        const float* cc = ntl ? c1 : c0;
        const int colb = (nh * 2 + ntl) * 8 + tig * 2;
        if (colb < 26) {
            g_part[h][rbc][arow0][colb]     = cc[0];
            g_part[h][rbc][arow0 + 8][colb] = cc[2];
            if (colb + 1 < 26) {
                g_part[h][rbc][arow0][colb + 1]     = cc[1];
                g_part[h][rbc][arow0 + 8][colb + 1] = cc[3];
            }
        }
    }

    __threadfence();
    __syncthreads();
    if (tid == 0) s_flag = atomicAdd(&g_ctr[rbc], 1);
    __syncthreads();

    // ---- last of the 2 CTAs for this row block finishes ----
    if (s_flag == NSPLIT - 1) {
        if (tid < NS)
            s_sn[tid] = g_snh[0][rbc][tid] + g_snh[1][rbc][tid];
        __syncthreads();
        if (tid < MR) {
            const int r = tid;
            float dt[NS];
            #pragma unroll
            for (int s = 0; s < NS; ++s) dt[s] = 0.f;
            float qnT = 0.f, qsT = 0.f;
            #pragma unroll
            for (int q = 0; q < NSPLIT; ++q) {
                #pragma unroll
                for (int s = 0; s < NS; ++s) dt[s] += g_part[q][rbc][r][s];
                qsT += g_part[q][rbc][r][25];
                qnT += g_part[q][rbc][r][26];
            }
            // d2 = qn + (ssq + 2 eps ssm) + D eps^2 - 2 dot - 2 eps qsum
            const float base = qnT - 2.f * EPSV * qsT + (float)D * (EPSV * EPSV);
            #pragma unroll
            for (int wy = 0; wy < NWAY; ++wy) {
                float sum = 0.f;
                #pragma unroll
                for (int k = 0; k < KSHOT; ++k) {
                    const int s = wy * KSHOT + k;
                    const float d2 = base + s_sn[s] - 2.f * dt[s];
                    sum += sqrtf(fmaxf(d2, 0.f));
                }
                out[(size_t)(rbc * MR + r) * NWAY + wy] = -sum;
            }
        }
        if (tid == 0) g_ctr[rbc] = 0;   // reset for next replay
    }
}

// ---------------------------------------------------------------------------
extern "C" void kernel_launch(void* const* d_in, const int* in_sizes, int n_in,
                              void* d_out, int out_size) {
    const float* support = (const float*)d_in[0];
    const float* query   = (const float*)d_in[1];
    if (n_in >= 2 && in_sizes[0] > in_sizes[1]) {
        const float* t = support; support = query; query = t;
    }
    float* out = (float*)d_out;

    cudaFuncSetAttribute(pd_mma, cudaFuncAttributeMaxDynamicSharedMemorySize,
                         DSMEM);
    pd_mma<<<dim3(NRB, NSPLIT), THREADS, DSMEM>>>(support, query, out);
}

// round 11
// speedup vs baseline: 1.0880x; 1.0880x over previous
#include <cuda_runtime.h>
#include <cuda_bf16.h>
#include <math.h>
#include <string.h>

// support [25,2560] f32, query [4096,2560] f32 -> out [4096,5] f32
#define D       2560
#define NS      25
#define NSB     26              // 25 supports + 1 ones-row (gives qsum)
#define NPAD    32
#define NWAY    5
#define KSHOT   5
#define EPSV    1e-6f

#define NSPLIT  4
#define DQ      640             // K per CTA
#define MROWS   128             // query rows per CTA
#define NRB     32
#define THREADS 256
#define BSTRIDE 648             // bf16 elems per B smem row (conflict-free, R6-proven)

#define KSUB    64              // f32 cols per ring stage
#define NSTG    10              // DQ / KSUB
#define RING    4
#define ASTR    72              // f32 row stride in ring (8g+2t banks: conflict-free)
#define STAGEF  (MROWS * ASTR)              // floats per stage (9216)
#define DSMEM   (RING * STAGEF * 4)         // 147456 bytes

typedef unsigned long long u64;

__device__ float g_dot[NSPLIT][NRB][NSB][MROWS];
__device__ float g_qn [NSPLIT][NRB][MROWS];
__device__ float g_sn [NSPLIT][NS];
__device__ int   g_ctr[NRB];    // zero-init; self-resetting per launch

__device__ __forceinline__ u64 ffma2(u64 a, u64 b, u64 c) {
    u64 d;
    asm("fma.rn.f32x2 %0, %1, %2, %3;" : "=l"(d) : "l"(a), "l"(b), "l"(c));
    return d;
}
__device__ __forceinline__ float f2_sum(u64 v) {
    return __uint_as_float((unsigned)(v & 0xffffffffull)) +
           __uint_as_float((unsigned)(v >> 32));
}
__device__ __forceinline__ u64 as_u64(float2 v) {
    u64 r; memcpy(&r, &v, 8); return r;
}
__device__ __forceinline__ unsigned cvt_bf2(float2 v) {
    __nv_bfloat162 p = __floats2bfloat162_rn(v.x, v.y);
    unsigned r; memcpy(&r, &p, 4); return r;
}
__device__ __forceinline__ unsigned smem_u32(const void* p) {
    return (unsigned)__cvta_generic_to_shared(p);
}
__device__ __forceinline__ void mma16816(float c[4],
                                         unsigned a0, unsigned a1,
                                         unsigned a2, unsigned a3,
                                         unsigned b0, unsigned b1) {
    asm volatile(
        "mma.sync.aligned.m16n8k16.row.col.f32.bf16.bf16.f32 "
        "{%0,%1,%2,%3}, {%4,%5,%6,%7}, {%8,%9}, {%0,%1,%2,%3};"
        : "+f"(c[0]), "+f"(c[1]), "+f"(c[2]), "+f"(c[3])
        : "r"(a0), "r"(a1), "r"(a2), "r"(a3), "r"(b0), "r"(b1));
}
__device__ __forceinline__ void mbar_wait(unsigned addr, unsigned parity) {
    asm volatile(
        "{\n\t"
        ".reg .pred P;\n\t"
        "W_%=:\n\t"
        "mbarrier.try_wait.parity.acquire.cta.shared::cta.b64 P, [%0], %1;\n\t"
        "@P bra D_%=;\n\t"
        "bra W_%=;\n\t"
        "D_%=:\n\t"
        "}"
        :: "r"(addr), "r"(parity) : "memory");
}

// ---------------------------------------------------------------------------
// CTA = (row block rb: 128 rows, K-quarter qd). 8 warps, warp owns 16 rows.
// Query streamed via cp.async.bulk (TMA path) into a 4-slot x 36KB ring:
// 128 threads each bulk-copy one 256B row-slice per stage; completion on a
// per-slot mbarrier (count=128, each issuer expects its own 256B). Producers
// == consumers, so the post-consume __syncthreads is the empty barrier.
// B (support bf16, ones-row 25 for qsum) staged once. Epilogue = R7 finisher.
// ---------------------------------------------------------------------------
__global__ __launch_bounds__(THREADS, 1)
void pd_mma(const float* __restrict__ support,
            const float* __restrict__ query,
            float* __restrict__ out) {
    extern __shared__ float ring[];                 // [RING][MROWS][ASTR]
    __shared__ __align__(16) __nv_bfloat16 Bs[NPAD][BSTRIDE];
    __shared__ float s_red[NS][8][2];
    __shared__ float s_sn[NS];
    __shared__ __align__(8) u64 mbar[RING];
    __shared__ int   s_flag;

    const int tid  = threadIdx.x;
    const int warp = tid >> 5;
    const int ln   = tid & 31;
    const int gid  = ln >> 2;
    const int tig  = ln & 3;
    const int rb   = blockIdx.x;
    const int qd   = blockIdx.y;
    const int dstart = qd * DQ;

    if (tid == 0) {
        #pragma unroll
        for (int i = 0; i < RING; ++i)
            asm volatile("mbarrier.init.shared.b64 [%0], %1;"
                         :: "r"(smem_u32(&mbar[i])), "r"(128u) : "memory");
    }
    __syncthreads();   // barriers initialized before any arrive/bulk

    const float* qbase = query + (size_t)rb * MROWS * D + dstart;

    // ---- bulk stage issue: thread tid<128 copies row tid's 256B slice ----
    auto issue_stage = [&](int st) {
        if (st < NSTG && tid < MROWS) {
            const int slot = st & (RING - 1);
            const unsigned mb = smem_u32(&mbar[slot]);
            asm volatile("mbarrier.arrive.expect_tx.shared.b64 _, [%0], %1;"
                         :: "r"(mb), "r"(256u) : "memory");
            const float* src = qbase + (size_t)tid * D + st * KSUB;
            const unsigned dst = smem_u32(ring + slot * STAGEF + tid * ASTR);
            asm volatile(
                "cp.async.bulk.shared::cluster.global.mbarrier::complete_tx::bytes "
                "[%0], [%1], %2, [%3];"
                :: "r"(dst), "l"(src), "r"(256u), "r"(mb) : "memory");
        }
    };
    issue_stage(0); issue_stage(1); issue_stage(2); issue_stage(3);

    // ---- ones row (25) and zero pad rows (26..31) ----
    for (int i = tid; i < (NPAD - NS) * BSTRIDE; i += THREADS) {
        const int r = NS + i / BSTRIDE;
        const int c = i % BSTRIDE;
        Bs[r][c] = __float2bfloat16(r == NS ? 1.f : 0.f);
    }

    // ---- stage B: 25x640 f32 -> bf16 (rounded), plus ssq/ssm partials ----
    if (tid < NS * 8) {
        const int n  = tid >> 3;
        const int kc = tid & 7;                    // 80-col strip
        const float* src = support + (size_t)n * D + dstart + kc * 80;
        float ssq = 0.f, ssm = 0.f;
        #pragma unroll
        for (int j = 0; j < 20; ++j) {
            const float4 v = *reinterpret_cast<const float4*>(src + j * 4);
            const __nv_bfloat162 p0 = __floats2bfloat162_rn(v.x, v.y);
            const __nv_bfloat162 p1 = __floats2bfloat162_rn(v.z, v.w);
            const float r0 = __bfloat162float(p0.x), r1 = __bfloat162float(p0.y);
            const float r2 = __bfloat162float(p1.x), r3 = __bfloat162float(p1.y);
            ssq = fmaf(r0, r0, ssq); ssq = fmaf(r1, r1, ssq);
            ssq = fmaf(r2, r2, ssq); ssq = fmaf(r3, r3, ssq);
            ssm += (r0 + r1) + (r2 + r3);
            u64 u; memcpy(&u, &p0, 4); memcpy(((char*)&u) + 4, &p1, 4);
            *reinterpret_cast<u64*>(&Bs[n][kc * 80 + j * 4]) = u;
        }
        s_red[n][kc][0] = ssq;
        s_red[n][kc][1] = ssm;
    }
    __syncthreads();
    if (tid < NS) {
        float a = 0.f, b = 0.f;
        #pragma unroll
        for (int o = 0; o < 8; ++o) { a += s_red[tid][o][0]; b += s_red[tid][o][1]; }
        g_sn[qd][tid] = a + 2.f * EPSV * b;   // ||s~||^2 + 2 eps sum(s~) (quarter)
    }

    // ---- mainloop: 10 stages x 4 k16-chunks ----
    const int lrow = warp * 16 + gid;
    float c[4][4];
    #pragma unroll
    for (int nt = 0; nt < 4; ++nt)
        #pragma unroll
        for (int i = 0; i < 4; ++i) c[nt][i] = 0.f;
    u64 qn0 = 0ull, qn1 = 0ull;
    const __nv_bfloat16* brow = &Bs[gid][tig * 2];

    for (int st = 0; st < NSTG; ++st) {
        const int slot = st & (RING - 1);
        mbar_wait(smem_u32(&mbar[slot]), (st >> 2) & 1);
        const float* ap = ring + slot * STAGEF + lrow * ASTR + tig * 2;
        #pragma unroll
        for (int cc = 0; cc < 4; ++cc) {
            const int k = cc * 16;
            const float2 a0 = *reinterpret_cast<const float2*>(ap + k);
            const float2 a1 = *reinterpret_cast<const float2*>(ap + 8 * ASTR + k);
            const float2 a2 = *reinterpret_cast<const float2*>(ap + k + 8);
            const float2 a3 = *reinterpret_cast<const float2*>(ap + 8 * ASTR + k + 8);
            qn0 = ffma2(as_u64(a0), as_u64(a0), qn0);
            qn0 = ffma2(as_u64(a2), as_u64(a2), qn0);
            qn1 = ffma2(as_u64(a1), as_u64(a1), qn1);
            qn1 = ffma2(as_u64(a3), as_u64(a3), qn1);
            const unsigned ra0 = cvt_bf2(a0), ra1 = cvt_bf2(a1);
            const unsigned ra2 = cvt_bf2(a2), ra3 = cvt_bf2(a3);
            const int kg = st * KSUB + k;
            #pragma unroll
            for (int nt = 0; nt < 4; ++nt) {
                const __nv_bfloat16* bp = brow + nt * 8 * BSTRIDE + kg;
                const unsigned b0 = *reinterpret_cast<const unsigned*>(bp);
                const unsigned b1 = *reinterpret_cast<const unsigned*>(bp + 8);
                mma16816(c[nt], ra0, ra1, ra2, ra3, b0, b1);
            }
        }
        __syncthreads();       // all warps done reading slot -> safe to refill
        issue_stage(st + RING);
    }

    // ---- qn: reduce over the 4 quad lanes (same row) ----
    float q0 = f2_sum(qn0), q1 = f2_sum(qn1);
    q0 += __shfl_xor_sync(0xffffffffu, q0, 1);
    q0 += __shfl_xor_sync(0xffffffffu, q0, 2);
    q1 += __shfl_xor_sync(0xffffffffu, q1, 1);
    q1 += __shfl_xor_sync(0xffffffffu, q1, 2);
    if (tig == 0) {
        g_qn[qd][rb][lrow]     = q0;
        g_qn[qd][rb][lrow + 8] = q1;
    }

    // ---- publish dot partials (disjoint (row,col) per lane) ----
    #pragma unroll
    for (int nt = 0; nt < 4; ++nt) {
        const int s = nt * 8 + tig * 2;
        if (s < NSB) {
            g_dot[qd][rb][s][lrow]     = c[nt][0];
            g_dot[qd][rb][s][lrow + 8] = c[nt][2];
        }
        if (s + 1 < NSB) {
            g_dot[qd][rb][s + 1][lrow]     = c[nt][1];
            g_dot[qd][rb][s + 1][lrow + 8] = c[nt][3];
        }
    }

    __threadfence();
    __syncthreads();
    if (tid == 0) s_flag = atomicAdd(&g_ctr[rb], 1);
    __syncthreads();

    // ---- last CTA of this row block finishes ----
    if (s_flag == NSPLIT - 1) {
        if (tid < NS) {
            float a = 0.f;
            #pragma unroll
            for (int q = 0; q < NSPLIT; ++q) a += g_sn[q][tid];
            s_sn[tid] = a;
        }
        __syncthreads();
        if (tid < MROWS) {
            const int r = tid;
            float dt[NS];
            #pragma unroll
            for (int s = 0; s < NS; ++s) dt[s] = 0.f;
            float qnT = 0.f, qsT = 0.f;
            #pragma unroll
            for (int q = 0; q < NSPLIT; ++q) {
                #pragma unroll
                for (int s = 0; s < NS; ++s) dt[s] += g_dot[q][rb][s][r];
                qsT += g_dot[q][rb][25][r];     // ones-row dot = sum(q~)
                qnT += g_qn[q][rb][r];
            }
            // d2 = qn + (ssq + 2 eps ssm) + D eps^2 - 2 dot - 2 eps qsum
            const float base = qnT - 2.f * EPSV * qsT + (float)D * (EPSV * EPSV);
            #pragma unroll
            for (int w = 0; w < NWAY; ++w) {
                float sum = 0.f;
                #pragma unroll
                for (int k = 0; k < KSHOT; ++k) {
                    const int s = w * KSHOT + k;
                    const float d2 = base + s_sn[s] - 2.f * dt[s];
                    sum += sqrtf(fmaxf(d2, 0.f));
                }
                out[(size_t)(rb * MROWS + r) * NWAY + w] = -sum;
            }
        }
        if (tid == 0) g_ctr[rb] = 0;   // reset for next replay
    }
}

// ---------------------------------------------------------------------------
extern "C" void kernel_launch(void* const* d_in, const int* in_sizes, int n_in,
                              void* d_out, int out_size) {
    const float* support = (const float*)d_in[0];
    const float* query   = (const float*)d_in[1];
    if (n_in >= 2 && in_sizes[0] > in_sizes[1]) {
        const float* t = support; support = query; query = t;
    }
    float* out = (float*)d_out;

    cudaFuncSetAttribute(pd_mma, cudaFuncAttributeMaxDynamicSharedMemorySize,
                         DSMEM);
    pd_mma<<<dim3(NRB, NSPLIT), THREADS, DSMEM>>>(support, query, out);
}

// round 12
// speedup vs baseline: 1.0986x; 1.0097x over previous
#include <cuda_runtime.h>
#include <cuda_bf16.h>
#include <math.h>
#include <string.h>

// support [25,2560] f32, query [4096,2560] f32 -> out [4096,5] f32
#define D       2560
#define NS      25
#define NSB     26              // 25 supports + 1 ones-row (gives qsum)
#define NPAD    32
#define NWAY    5
#define KSHOT   5
#define EPSV    1e-6f

#define NSPLIT  4
#define DQ      640             // K per CTA
#define NCHUNK  40              // DQ / 16
#define MROWS   64              // query rows per CTA
#define NRB     64              // NQ / MROWS
#define THREADS 256
#define BSTRIDE 648             // bf16 elems per B smem row
#define PF      4               // A prefetch depth (chunks)

typedef unsigned long long u64;

__device__ float g_dot[NSPLIT][NRB][NSB][MROWS];   // 1.7 MB (8x smaller than R7)
__device__ float g_qn [NSPLIT][NRB][MROWS];
__device__ float g_sn [NSPLIT][NS];
__device__ int   g_ctr[NRB];    // zero-init; self-resetting per launch

__device__ __forceinline__ u64 ffma2(u64 a, u64 b, u64 c) {
    u64 d;
    asm("fma.rn.f32x2 %0, %1, %2, %3;" : "=l"(d) : "l"(a), "l"(b), "l"(c));
    return d;
}
__device__ __forceinline__ float f2_sum(u64 v) {
    return __uint_as_float((unsigned)(v & 0xffffffffull)) +
           __uint_as_float((unsigned)(v >> 32));
}
__device__ __forceinline__ unsigned cvt_bf2(float x, float y) {
    __nv_bfloat162 p = __floats2bfloat162_rn(x, y);
    unsigned r; memcpy(&r, &p, 4); return r;
}
__device__ __forceinline__ void mma16816(float c[4],
                                         unsigned a0, unsigned a1,
                                         unsigned a2, unsigned a3,
                                         unsigned b0, unsigned b1) {
    asm volatile(
        "mma.sync.aligned.m16n8k16.row.col.f32.bf16.bf16.f32 "
        "{%0,%1,%2,%3}, {%4,%5,%6,%7}, {%8,%9}, {%0,%1,%2,%3};"
        : "+f"(c[0]), "+f"(c[1]), "+f"(c[2]), "+f"(c[3])
        : "r"(a0), "r"(a1), "r"(a2), "r"(a3), "r"(b0), "r"(b1));
}

// ---------------------------------------------------------------------------
// CTA = (row block rb: 64 rows, K-quarter qd). 8 warps = 4 m-groups x 2
// n-halves (NO K-split inside the CTA -> 8x less partial traffic than R7).
//
// K-PERMUTATION TRICK: within each 16-col chunk, fragment slot tig's logical
// k {2t,2t+1,2t+8,2t+9} is assigned physical cols {4t..4t+3}. Both A and B
// use the same mapping, so the MMA accumulates the same dot product, but
// A loads become one contiguous float4 (LDG.128, 64B per quad) per row and
// B loads one LDS.64 per n-tile. qn/ssq/ssm are permutation-invariant.
//
// A: LDG.128 direct from global, PF=4 register pipeline. B: support bf16
// staged once in smem (row 25 = ones -> qsum free). R7-proven finisher.
// ---------------------------------------------------------------------------
__global__ __launch_bounds__(THREADS, 2)
void pd_mma(const float* __restrict__ support,
            const float* __restrict__ query,
            float* __restrict__ out) {
    __shared__ __align__(16) __nv_bfloat16 Bs[NPAD][BSTRIDE];
    __shared__ float s_red[NS][8][2];
    __shared__ float s_sn[NS];
    __shared__ int   s_flag;

    const int tid  = threadIdx.x;
    const int warp = tid >> 5;
    const int ln   = tid & 31;
    const int gid  = ln >> 2;
    const int tig  = ln & 3;
    const int mg   = warp >> 1;      // m-group 0..3 (16 rows each)
    const int nhf  = warp & 1;       // n-half: n-tiles nhf*2, nhf*2+1
    const int rb   = blockIdx.x;
    const int qd   = blockIdx.y;
    const int dstart = qd * DQ;

    // ---- ones row (25) and zero pad rows (26..31) ----
    for (int i = tid; i < (NPAD - NS) * BSTRIDE; i += THREADS) {
        const int r = NS + i / BSTRIDE;
        const int c = i % BSTRIDE;
        Bs[r][c] = __float2bfloat16(r == NS ? 1.f : 0.f);
    }

    // ---- stage B: 25x640 f32 -> bf16 (rounded), plus ssq/ssm partials ----
    if (tid < NS * 8) {
        const int n  = tid >> 3;
        const int kc = tid & 7;                    // 80-col strip
        const float* src = support + (size_t)n * D + dstart + kc * 80;
        float ssq = 0.f, ssm = 0.f;
        #pragma unroll
        for (int j = 0; j < 20; ++j) {
            const float4 v = *reinterpret_cast<const float4*>(src + j * 4);
            const __nv_bfloat162 p0 = __floats2bfloat162_rn(v.x, v.y);
            const __nv_bfloat162 p1 = __floats2bfloat162_rn(v.z, v.w);
            const float r0 = __bfloat162float(p0.x), r1 = __bfloat162float(p0.y);
            const float r2 = __bfloat162float(p1.x), r3 = __bfloat162float(p1.y);
            ssq = fmaf(r0, r0, ssq); ssq = fmaf(r1, r1, ssq);
            ssq = fmaf(r2, r2, ssq); ssq = fmaf(r3, r3, ssq);
            ssm += (r0 + r1) + (r2 + r3);
            u64 u; memcpy(&u, &p0, 4); memcpy(((char*)&u) + 4, &p1, 4);
            *reinterpret_cast<u64*>(&Bs[n][kc * 80 + j * 4]) = u;
        }
        s_red[n][kc][0] = ssq;
        s_red[n][kc][1] = ssm;
    }
    __syncthreads();
    if (tid < NS) {
        float a = 0.f, b = 0.f;
        #pragma unroll
        for (int o = 0; o < 8; ++o) { a += s_red[tid][o][0]; b += s_red[tid][o][1]; }
        g_sn[qd][tid] = a + 2.f * EPSV * b;   // ||s~||^2 + 2 eps sum(s~) (quarter)
    }

    // ---- mainloop: 40 chunks of 16 cols, LDG.128 A, PF=4 ----
    const int lrow = mg * 16 + gid;
    const float* qa = query + (size_t)(rb * MROWS + lrow) * D + dstart + tig * 4;
    const float* qb = qa + (size_t)8 * D;

    float c[2][4];
    #pragma unroll
    for (int nt = 0; nt < 2; ++nt)
        #pragma unroll
        for (int i = 0; i < 4; ++i) c[nt][i] = 0.f;
    u64 qn0 = 0ull, qn1 = 0ull;

    // B row bases for this warp's two n-tiles (this lane's 8B slice)
    const __nv_bfloat16* bbase0 = &Bs[(nhf * 2)     * 8 + gid][tig * 4];
    const __nv_bfloat16* bbase1 = &Bs[(nhf * 2 + 1) * 8 + gid][tig * 4];

    float4 pa[PF][2];
    #pragma unroll
    for (int p = 0; p < PF; ++p) {
        pa[p][0] = *reinterpret_cast<const float4*>(qa + p * 16);
        pa[p][1] = *reinterpret_cast<const float4*>(qb + p * 16);
    }

    #pragma unroll
    for (int ch = 0; ch < NCHUNK; ++ch) {
        const int slot = ch & (PF - 1);
        const float4 vA = pa[slot][0];
        const float4 vB = pa[slot][1];
        if (ch + PF < NCHUNK) {
            pa[slot][0] = *reinterpret_cast<const float4*>(qa + (ch + PF) * 16);
            pa[slot][1] = *reinterpret_cast<const float4*>(qb + (ch + PF) * 16);
        }
        if (nhf == 0) {                    // qn from raw f32 (one owner per row)
            u64 lo, hi;
            memcpy(&lo, &vA.x, 8); memcpy(&hi, &vA.z, 8);
            qn0 = ffma2(lo, lo, qn0); qn0 = ffma2(hi, hi, qn0);
            memcpy(&lo, &vB.x, 8); memcpy(&hi, &vB.z, 8);
            qn1 = ffma2(lo, lo, qn1); qn1 = ffma2(hi, hi, qn1);
        }
        const unsigned ra0 = cvt_bf2(vA.x, vA.y);
        const unsigned ra2 = cvt_bf2(vA.z, vA.w);
        const unsigned ra1 = cvt_bf2(vB.x, vB.y);
        const unsigned ra3 = cvt_bf2(vB.z, vB.w);

        const u64 bv0 = *reinterpret_cast<const u64*>(bbase0 + ch * 16);
        const u64 bv1 = *reinterpret_cast<const u64*>(bbase1 + ch * 16);
        mma16816(c[0], ra0, ra1, ra2, ra3,
                 (unsigned)(bv0 & 0xffffffffull), (unsigned)(bv0 >> 32));
        mma16816(c[1], ra0, ra1, ra2, ra3,
                 (unsigned)(bv1 & 0xffffffffull), (unsigned)(bv1 >> 32));
    }

    // ---- qn: reduce over the 4 quad lanes (same row) ----
    if (nhf == 0) {
        float q0 = f2_sum(qn0), q1 = f2_sum(qn1);
        q0 += __shfl_xor_sync(0xffffffffu, q0, 1);
        q0 += __shfl_xor_sync(0xffffffffu, q0, 2);
        q1 += __shfl_xor_sync(0xffffffffu, q1, 1);
        q1 += __shfl_xor_sync(0xffffffffu, q1, 2);
        if (tig == 0) {
            g_qn[qd][rb][lrow]     = q0;
            g_qn[qd][rb][lrow + 8] = q1;
        }
    }

    // ---- publish dot partials (disjoint (row,col) per lane) ----
    #pragma unroll
    for (int ntl = 0; ntl < 2; ++ntl) {
        const int s = (nhf * 2 + ntl) * 8 + tig * 2;
        if (s < NSB) {
            g_dot[qd][rb][s][lrow]     = c[ntl][0];
            g_dot[qd][rb][s][lrow + 8] = c[ntl][2];
        }
        if (s + 1 < NSB) {
            g_dot[qd][rb][s + 1][lrow]     = c[ntl][1];
            g_dot[qd][rb][s + 1][lrow + 8] = c[ntl][3];
        }
    }

    __threadfence();
    __syncthreads();
    if (tid == 0) s_flag = atomicAdd(&g_ctr[rb], 1);
    __syncthreads();

    // ---- last CTA of this row block finishes ----
    if (s_flag == NSPLIT - 1) {
        if (tid < NS) {
            float a = 0.f;
            #pragma unroll
            for (int q = 0; q < NSPLIT; ++q) a += g_sn[q][tid];
            s_sn[tid] = a;
        }
        __syncthreads();
        if (tid < MROWS) {
            const int r = tid;
            float dt[NS];
            #pragma unroll
            for (int s = 0; s < NS; ++s) dt[s] = 0.f;
            float qnT = 0.f, qsT = 0.f;
            #pragma unroll
            for (int q = 0; q < NSPLIT; ++q) {
                #pragma unroll
                for (int s = 0; s < NS; ++s) dt[s] += g_dot[q][rb][s][r];
                qsT += g_dot[q][rb][25][r];     // ones-row dot = sum(q~)
                qnT += g_qn[q][rb][r];
            }
            // d2 = qn + (ssq + 2 eps ssm) + D eps^2 - 2 dot - 2 eps qsum
            const float base = qnT - 2.f * EPSV * qsT + (float)D * (EPSV * EPSV);
            #pragma unroll
            for (int w = 0; w < NWAY; ++w) {
                float sum = 0.f;
                #pragma unroll
                for (int k = 0; k < KSHOT; ++k) {
                    const int s = w * KSHOT + k;
                    const float d2 = base + s_sn[s] - 2.f * dt[s];
                    sum += sqrtf(fmaxf(d2, 0.f));
                }
                out[(size_t)(rb * MROWS + r) * NWAY + w] = -sum;
            }
        }
        if (tid == 0) g_ctr[rb] = 0;   // reset for next replay
    }
}

// ---------------------------------------------------------------------------
extern "C" void kernel_launch(void* const* d_in, const int* in_sizes, int n_in,
                              void* d_out, int out_size) {
    const float* support = (const float*)d_in[0];
    const float* query   = (const float*)d_in[1];
    if (n_in >= 2 && in_sizes[0] > in_sizes[1]) {
        const float* t = support; support = query; query = t;
    }
    float* out = (float*)d_out;

    pd_mma<<<dim3(NRB, NSPLIT), THREADS>>>(support, query, out);
}

// round 13
// speedup vs baseline: 1.1564x; 1.0526x over previous
#include <cuda_runtime.h>
#include <cuda_bf16.h>
#include <math.h>
#include <string.h>

// support [25,2560] f32, query [4096,2560] f32 -> out [4096,5] f32
#define D       2560
#define NS      25
#define NSB     26              // 25 supports + 1 ones-row (gives qsum)
#define NPAD    32
#define NWAY    5
#define KSHOT   5
#define EPSV    1e-6f

#define NSPLIT  8
#define DQ      320             // K per CTA
#define NCHUNK  20              // DQ / 16
#define MROWS   64              // query rows per CTA (4 warps x 16)
#define NRB     64              // NQ / MROWS
#define THREADS 128
#define BSTRIDE 328             // bf16 elems per B smem row (bank 4g+t: conflict-free)
#define PF      6               // A prefetch depth (chunks)

typedef unsigned long long u64;

__device__ float g_dot[NSPLIT][NRB][NSB][MROWS];   // 3.4 MB
__device__ float g_qn [NSPLIT][NRB][MROWS];
__device__ float g_sn [NSPLIT][NS];
__device__ int   g_ctr[NRB];    // zero-init; self-resetting per launch

__device__ __forceinline__ u64 ffma2(u64 a, u64 b, u64 c) {
    u64 d;
    asm("fma.rn.f32x2 %0, %1, %2, %3;" : "=l"(d) : "l"(a), "l"(b), "l"(c));
    return d;
}
__device__ __forceinline__ float f2_sum(u64 v) {
    return __uint_as_float((unsigned)(v & 0xffffffffull)) +
           __uint_as_float((unsigned)(v >> 32));
}
__device__ __forceinline__ u64 as_u64(float2 v) {
    u64 r; memcpy(&r, &v, 8); return r;
}
__device__ __forceinline__ unsigned cvt_bf2(float2 v) {
    __nv_bfloat162 p = __floats2bfloat162_rn(v.x, v.y);
    unsigned r; memcpy(&r, &p, 4); return r;
}
__device__ __forceinline__ void mma16816(float c[4],
                                         unsigned a0, unsigned a1,
                                         unsigned a2, unsigned a3,
                                         unsigned b0, unsigned b1) {
    asm volatile(
        "mma.sync.aligned.m16n8k16.row.col.f32.bf16.bf16.f32 "
        "{%0,%1,%2,%3}, {%4,%5,%6,%7}, {%8,%9}, {%0,%1,%2,%3};"
        : "+f"(c[0]), "+f"(c[1]), "+f"(c[2]), "+f"(c[3])
        : "r"(a0), "r"(a1), "r"(a2), "r"(a3), "r"(b0), "r"(b1));
}

// ---------------------------------------------------------------------------
// R7 champion re-parameterized for 4 CTAs/SM: CTA = (row block rb: 64 rows,
// K-eighth qd), 4 warps, warp owns 16 rows x full DQ (disjoint A data).
// PF=6 register prefetch -> 24 outstanding LDG.64 per warp (6 KB in flight,
// ~14 MB chip-wide). B (support bf16) staged once per CTA; row 25 = ones so
// the MMA emits sum(q~) free. fp32 qn from the same raw loads. Last CTA per
// row block fuses the sqrt/way-sum epilogue.
// ---------------------------------------------------------------------------
__global__ __launch_bounds__(THREADS, 4)
void pd_mma(const float* __restrict__ support,
            const float* __restrict__ query,
            float* __restrict__ out) {
    __shared__ __align__(16) __nv_bfloat16 Bs[NPAD][BSTRIDE];
    __shared__ float s_red[NS][4][2];
    __shared__ float s_sn[NS];
    __shared__ int   s_flag;

    const int tid  = threadIdx.x;
    const int warp = tid >> 5;
    const int ln   = tid & 31;
    const int gid  = ln >> 2;
    const int tig  = ln & 3;
    const int rb   = blockIdx.x;
    const int qd   = blockIdx.y;
    const int dstart = qd * DQ;

    // ---- ones row (25) and zero pad rows (26..31) ----
    for (int i = tid; i < (NPAD - NS) * BSTRIDE; i += THREADS) {
        const int r = NS + i / BSTRIDE;
        const int c = i % BSTRIDE;
        Bs[r][c] = __float2bfloat16(r == NS ? 1.f : 0.f);
    }

    // ---- stage B: 25x320 f32 -> bf16 (rounded), plus ssq/ssm partials ----
    if (tid < NS * 4) {
        const int n  = tid >> 2;
        const int kc = tid & 3;                    // 80-col strip
        const float* src = support + (size_t)n * D + dstart + kc * 80;
        float ssq = 0.f, ssm = 0.f;
        #pragma unroll
        for (int j = 0; j < 20; ++j) {
            const float4 v = *reinterpret_cast<const float4*>(src + j * 4);
            const __nv_bfloat162 p0 = __floats2bfloat162_rn(v.x, v.y);
            const __nv_bfloat162 p1 = __floats2bfloat162_rn(v.z, v.w);
            const float r0 = __bfloat162float(p0.x), r1 = __bfloat162float(p0.y);
            const float r2 = __bfloat162float(p1.x), r3 = __bfloat162float(p1.y);
            ssq = fmaf(r0, r0, ssq); ssq = fmaf(r1, r1, ssq);
            ssq = fmaf(r2, r2, ssq); ssq = fmaf(r3, r3, ssq);
            ssm += (r0 + r1) + (r2 + r3);
            u64 u; memcpy(&u, &p0, 4); memcpy(((char*)&u) + 4, &p1, 4);
            *reinterpret_cast<u64*>(&Bs[n][kc * 80 + j * 4]) = u;
        }
        s_red[n][kc][0] = ssq;
        s_red[n][kc][1] = ssm;
    }
    __syncthreads();
    if (tid < NS) {
        float a = 0.f, b = 0.f;
        #pragma unroll
        for (int o = 0; o < 4; ++o) { a += s_red[tid][o][0]; b += s_red[tid][o][1]; }
        g_sn[qd][tid] = a + 2.f * EPSV * b;   // ||s~||^2 + 2 eps sum(s~) (eighth)
    }

    // ---- mainloop: 20 k-chunks of 16, 4 n-tiles, PF=6 register pipeline ----
    const int lrow = warp * 16 + gid;
    const float* qa = query + (size_t)(rb * MROWS + lrow) * D + dstart + tig * 2;
    const float* qb = qa + (size_t)8 * D;

    float c[4][4];
    #pragma unroll
    for (int nt = 0; nt < 4; ++nt)
        #pragma unroll
        for (int i = 0; i < 4; ++i) c[nt][i] = 0.f;
    u64 qn0 = 0ull, qn1 = 0ull;
    const __nv_bfloat16* brow = &Bs[gid][tig * 2];

    float2 pa[PF][4];
    #pragma unroll
    for (int p = 0; p < PF; ++p) {
        const int k0 = p * 16;
        pa[p][0] = __ldg(reinterpret_cast<const float2*>(qa + k0));
        pa[p][1] = __ldg(reinterpret_cast<const float2*>(qb + k0));
        pa[p][2] = __ldg(reinterpret_cast<const float2*>(qa + k0 + 8));
        pa[p][3] = __ldg(reinterpret_cast<const float2*>(qb + k0 + 8));
    }

    #pragma unroll
    for (int ch = 0; ch < NCHUNK; ++ch) {
        const int slot = ch % PF;          // compile-time under full unroll
        const float2 a0 = pa[slot][0];
        const float2 a1 = pa[slot][1];
        const float2 a2 = pa[slot][2];
        const float2 a3 = pa[slot][3];
        if (ch + PF < NCHUNK) {
            const int k0 = (ch + PF) * 16;
            pa[slot][0] = __ldg(reinterpret_cast<const float2*>(qa + k0));
            pa[slot][1] = __ldg(reinterpret_cast<const float2*>(qb + k0));
            pa[slot][2] = __ldg(reinterpret_cast<const float2*>(qa + k0 + 8));
            pa[slot][3] = __ldg(reinterpret_cast<const float2*>(qb + k0 + 8));
        }
        qn0 = ffma2(as_u64(a0), as_u64(a0), qn0);
        qn0 = ffma2(as_u64(a2), as_u64(a2), qn0);
        qn1 = ffma2(as_u64(a1), as_u64(a1), qn1);
        qn1 = ffma2(as_u64(a3), as_u64(a3), qn1);
        const unsigned ra0 = cvt_bf2(a0);
        const unsigned ra1 = cvt_bf2(a1);
        const unsigned ra2 = cvt_bf2(a2);
        const unsigned ra3 = cvt_bf2(a3);
        const int k0 = ch * 16;
        #pragma unroll
        for (int nt = 0; nt < 4; ++nt) {
            const __nv_bfloat16* bp = brow + nt * 8 * BSTRIDE + k0;
            const unsigned b0 = *reinterpret_cast<const unsigned*>(bp);
            const unsigned b1 = *reinterpret_cast<const unsigned*>(bp + 8);
            mma16816(c[nt], ra0, ra1, ra2, ra3, b0, b1);
        }
    }

    // ---- qn: reduce over the 4 quad lanes (same row) ----
    float q0 = f2_sum(qn0), q1 = f2_sum(qn1);
    q0 += __shfl_xor_sync(0xffffffffu, q0, 1);
    q0 += __shfl_xor_sync(0xffffffffu, q0, 2);
    q1 += __shfl_xor_sync(0xffffffffu, q1, 1);
    q1 += __shfl_xor_sync(0xffffffffu, q1, 2);
    if (tig == 0) {
        g_qn[qd][rb][lrow]     = q0;
        g_qn[qd][rb][lrow + 8] = q1;
    }

    // ---- publish dot partials (disjoint (row,col) per lane) ----
    #pragma unroll
    for (int nt = 0; nt < 4; ++nt) {
        const int s = nt * 8 + tig * 2;
        if (s < NSB) {
            g_dot[qd][rb][s][lrow]     = c[nt][0];
            g_dot[qd][rb][s][lrow + 8] = c[nt][2];
        }
        if (s + 1 < NSB) {
            g_dot[qd][rb][s + 1][lrow]     = c[nt][1];
            g_dot[qd][rb][s + 1][lrow + 8] = c[nt][3];
        }
    }

    __threadfence();
    __syncthreads();
    if (tid == 0) s_flag = atomicAdd(&g_ctr[rb], 1);
    __syncthreads();

    // ---- last CTA of this row block finishes ----
    if (s_flag == NSPLIT - 1) {
        if (tid < NS) {
            float a = 0.f;
            #pragma unroll
            for (int q = 0; q < NSPLIT; ++q) a += g_sn[q][tid];
            s_sn[tid] = a;
        }
        __syncthreads();
        if (tid < MROWS) {
            const int r = tid;
            float dt[NS];
            #pragma unroll
            for (int s = 0; s < NS; ++s) dt[s] = 0.f;
            float qnT = 0.f, qsT = 0.f;
            #pragma unroll
            for (int q = 0; q < NSPLIT; ++q) {
                #pragma unroll
                for (int s = 0; s < NS; ++s) dt[s] += g_dot[q][rb][s][r];
                qsT += g_dot[q][rb][25][r];     // ones-row dot = sum(q~)
                qnT += g_qn[q][rb][r];
            }
            // d2 = qn + (ssq + 2 eps ssm) + D eps^2 - 2 dot - 2 eps qsum
            const float base = qnT - 2.f * EPSV * qsT + (float)D * (EPSV * EPSV);
            #pragma unroll
            for (int w = 0; w < NWAY; ++w) {
                float sum = 0.f;
                #pragma unroll
                for (int k = 0; k < KSHOT; ++k) {
                    const int s = w * KSHOT + k;
                    const float d2 = base + s_sn[s] - 2.f * dt[s];
                    sum += sqrtf(fmaxf(d2, 0.f));
                }
                out[(size_t)(rb * MROWS + r) * NWAY + w] = -sum;
            }
        }
        if (tid == 0) g_ctr[rb] = 0;   // reset for next replay
    }
}

// ---------------------------------------------------------------------------
extern "C" void kernel_launch(void* const* d_in, const int* in_sizes, int n_in,
                              void* d_out, int out_size) {
    const float* support = (const float*)d_in[0];
    const float* query   = (const float*)d_in[1];
    if (n_in >= 2 && in_sizes[0] > in_sizes[1]) {
        const float* t = support; support = query; query = t;
    }
    float* out = (float*)d_out;

    pd_mma<<<dim3(NRB, NSPLIT), THREADS>>>(support, query, out);
}

// round 14
// speedup vs baseline: 1.4757x; 1.2761x over previous
#include <cuda_runtime.h>
#include <cuda_bf16.h>
#include <math.h>
#include <string.h>

// support [25,2560] f32, query [4096,2560] f32 -> out [4096,5] f32
#define D       2560
#define NS      25
#define NSB     26              // 25 supports + 1 ones-row (gives qsum)
#define NPAD    32
#define NWAY    5
#define KSHOT   5
#define EPSV    1e-6f

#define NSPLIT  8
#define DQ      320             // K per CTA
#define NCHUNK  20              // DQ / 16
#define MROWS   128             // query rows per CTA
#define NRB     32              // NQ / MROWS
#define THREADS 256
#define BSTRIDE 336             // bf16/row: offset 168 fl = 8 banks -> LDS.64 conflict-free
#define PF      4               // A prefetch depth (chunks)

typedef unsigned long long u64;

__device__ float g_dot[NSPLIT][NRB][NSB][MROWS];
__device__ float g_qn [NSPLIT][NRB][MROWS];
__device__ float g_sn [NSPLIT][NS];
__device__ int   g_ctr[NRB];    // zero-init; self-resetting per launch

__device__ __forceinline__ u64 ffma2(u64 a, u64 b, u64 c) {
    u64 d;
    asm("fma.rn.f32x2 %0, %1, %2, %3;" : "=l"(d) : "l"(a), "l"(b), "l"(c));
    return d;
}
__device__ __forceinline__ float f2_sum(u64 v) {
    return __uint_as_float((unsigned)(v & 0xffffffffull)) +
           __uint_as_float((unsigned)(v >> 32));
}
__device__ __forceinline__ unsigned cvt_bf2(float x, float y) {
    __nv_bfloat162 p = __floats2bfloat162_rn(x, y);
    unsigned r; memcpy(&r, &p, 4); return r;
}
__device__ __forceinline__ void mma16816(float c[4],
                                         unsigned a0, unsigned a1,
                                         unsigned a2, unsigned a3,
                                         unsigned b0, unsigned b1) {
    asm volatile(
        "mma.sync.aligned.m16n8k16.row.col.f32.bf16.bf16.f32 "
        "{%0,%1,%2,%3}, {%4,%5,%6,%7}, {%8,%9}, {%0,%1,%2,%3};"
        : "+f"(c[0]), "+f"(c[1]), "+f"(c[2]), "+f"(c[3])
        : "r"(a0), "r"(a1), "r"(a2), "r"(a3), "r"(b0), "r"(b1));
}

// ---------------------------------------------------------------------------
// R7 champion + physical-k fragment mapping (R12-verified):
// Within each 16-col chunk, fragment slot tig carries PHYSICAL cols
// 4t..4t+3 on BOTH the A and B side (slot pairing: {4t,4t+1}->(a0,b0),
// {4t+2,4t+3}->(a2,b1)). The MMA sums a_slot*b_slot over matching physical
// columns, so the dot product is exact while:
//   A loads become ONE float4 (LDG.128) per row per chunk (contiguous quad)
//   B loads become ONE LDS.64 per n-tile (conflict-free @ BSTRIDE=336)
// CTA = (row block rb: 128 rows, K-eighth qd), 8 warps x 16 rows, occ 2.
// B staged once (row 25 = ones -> qsum free); fp32 qn from raw loads;
// last-CTA-per-rowblock fused finisher.
// ---------------------------------------------------------------------------
__global__ __launch_bounds__(THREADS, 2)
void pd_mma(const float* __restrict__ support,
            const float* __restrict__ query,
            float* __restrict__ out) {
    __shared__ __align__(16) __nv_bfloat16 Bs[NPAD][BSTRIDE];
    __shared__ float s_red[NS][8][2];
    __shared__ float s_sn[NS];
    __shared__ int   s_flag;

    const int tid  = threadIdx.x;
    const int warp = tid >> 5;
    const int ln   = tid & 31;
    const int gid  = ln >> 2;
    const int tig  = ln & 3;
    const int rb   = blockIdx.x;
    const int qd   = blockIdx.y;
    const int dstart = qd * DQ;

    // ---- ones row (25) and zero pad rows (26..31) ----
    for (int i = tid; i < (NPAD - NS) * BSTRIDE; i += THREADS) {
        const int r = NS + i / BSTRIDE;
        const int c = i % BSTRIDE;
        Bs[r][c] = __float2bfloat16(r == NS ? 1.f : 0.f);
    }

    // ---- stage B: 25x320 f32 -> bf16 (rounded), plus ssq/ssm partials ----
    if (tid < NS * 8) {
        const int n  = tid >> 3;
        const int kc = tid & 7;                    // 40-col strip
        const float* src = support + (size_t)n * D + dstart + kc * 40;
        float ssq = 0.f, ssm = 0.f;
        #pragma unroll
        for (int j = 0; j < 10; ++j) {
            const float4 v = *reinterpret_cast<const float4*>(src + j * 4);
            const __nv_bfloat162 p0 = __floats2bfloat162_rn(v.x, v.y);
            const __nv_bfloat162 p1 = __floats2bfloat162_rn(v.z, v.w);
            const float r0 = __bfloat162float(p0.x), r1 = __bfloat162float(p0.y);
            const float r2 = __bfloat162float(p1.x), r3 = __bfloat162float(p1.y);
            ssq = fmaf(r0, r0, ssq); ssq = fmaf(r1, r1, ssq);
            ssq = fmaf(r2, r2, ssq); ssq = fmaf(r3, r3, ssq);
            ssm += (r0 + r1) + (r2 + r3);
            u64 u; memcpy(&u, &p0, 4); memcpy(((char*)&u) + 4, &p1, 4);
            *reinterpret_cast<u64*>(&Bs[n][kc * 40 + j * 4]) = u;
        }
        s_red[n][kc][0] = ssq;
        s_red[n][kc][1] = ssm;
    }
    __syncthreads();
    if (tid < NS) {
        float a = 0.f, b = 0.f;
        #pragma unroll
        for (int o = 0; o < 8; ++o) { a += s_red[tid][o][0]; b += s_red[tid][o][1]; }
        g_sn[qd][tid] = a + 2.f * EPSV * b;   // ||s~||^2 + 2 eps sum(s~) (eighth)
    }

    // ---- mainloop: 20 k-chunks of 16, 4 n-tiles, LDG.128 A, PF=4 ----
    const int lrow = warp * 16 + gid;
    const float* qa = query + (size_t)(rb * MROWS + lrow) * D + dstart + tig * 4;
    const float* qb = qa + (size_t)8 * D;

    float c[4][4];
    #pragma unroll
    for (int nt = 0; nt < 4; ++nt)
        #pragma unroll
        for (int i = 0; i < 4; ++i) c[nt][i] = 0.f;
    u64 qn0 = 0ull, qn1 = 0ull;

    float4 pa[PF][2];
    #pragma unroll
    for (int p = 0; p < PF; ++p) {
        pa[p][0] = *reinterpret_cast<const float4*>(qa + p * 16);
        pa[p][1] = *reinterpret_cast<const float4*>(qb + p * 16);
    }

    #pragma unroll
    for (int ch = 0; ch < NCHUNK; ++ch) {
        const int slot = ch & (PF - 1);
        const float4 vA = pa[slot][0];
        const float4 vB = pa[slot][1];
        if (ch + PF < NCHUNK) {
            pa[slot][0] = *reinterpret_cast<const float4*>(qa + (ch + PF) * 16);
            pa[slot][1] = *reinterpret_cast<const float4*>(qb + (ch + PF) * 16);
        }
        {   // fp32 qn from the raw values (permutation-invariant)
            u64 lo, hi;
            memcpy(&lo, &vA.x, 8); memcpy(&hi, &vA.z, 8);
            qn0 = ffma2(lo, lo, qn0); qn0 = ffma2(hi, hi, qn0);
            memcpy(&lo, &vB.x, 8); memcpy(&hi, &vB.z, 8);
            qn1 = ffma2(lo, lo, qn1); qn1 = ffma2(hi, hi, qn1);
        }
        const unsigned ra0 = cvt_bf2(vA.x, vA.y);   // phys 4t,4t+1
        const unsigned ra2 = cvt_bf2(vA.z, vA.w);   // phys 4t+2,4t+3
        const unsigned ra1 = cvt_bf2(vB.x, vB.y);
        const unsigned ra3 = cvt_bf2(vB.z, vB.w);
        const int k0 = ch * 16 + tig * 4;
        #pragma unroll
        for (int nt = 0; nt < 4; ++nt) {
            const u64 bv = *reinterpret_cast<const u64*>(&Bs[nt * 8 + gid][k0]);
            mma16816(c[nt], ra0, ra1, ra2, ra3,
                     (unsigned)(bv & 0xffffffffull), (unsigned)(bv >> 32));
        }
    }

    // ---- qn: reduce over the 4 quad lanes (same row) ----
    float q0 = f2_sum(qn0), q1 = f2_sum(qn1);
    q0 += __shfl_xor_sync(0xffffffffu, q0, 1);
    q0 += __shfl_xor_sync(0xffffffffu, q0, 2);
    q1 += __shfl_xor_sync(0xffffffffu, q1, 1);
    q1 += __shfl_xor_sync(0xffffffffu, q1, 2);
    if (tig == 0) {
        g_qn[qd][rb][lrow]     = q0;
        g_qn[qd][rb][lrow + 8] = q1;
    }

    // ---- publish dot partials (disjoint (row,col) per lane) ----
    #pragma unroll
    for (int nt = 0; nt < 4; ++nt) {
        const int s = nt * 8 + tig * 2;
        if (s < NSB) {
            g_dot[qd][rb][s][lrow]     = c[nt][0];
            g_dot[qd][rb][s][lrow + 8] = c[nt][2];
        }
        if (s + 1 < NSB) {
            g_dot[qd][rb][s + 1][lrow]     = c[nt][1];
            g_dot[qd][rb][s + 1][lrow + 8] = c[nt][3];
        }
    }

    __threadfence();
    __syncthreads();
    if (tid == 0) s_flag = atomicAdd(&g_ctr[rb], 1);
    __syncthreads();

    // ---- last CTA of this row block finishes ----
    if (s_flag == NSPLIT - 1) {
        if (tid < NS) {
            float a = 0.f;
            #pragma unroll
            for (int q = 0; q < NSPLIT; ++q) a += g_sn[q][tid];
            s_sn[tid] = a;
        }
        __syncthreads();
        if (tid < MROWS) {
            const int r = tid;
            float dt[NS];
            #pragma unroll
            for (int s = 0; s < NS; ++s) dt[s] = 0.f;
            float qnT = 0.f, qsT = 0.f;
            #pragma unroll
            for (int q = 0; q < NSPLIT; ++q) {
                #pragma unroll
                for (int s = 0; s < NS; ++s) dt[s] += g_dot[q][rb][s][r];
                qsT += g_dot[q][rb][25][r];     // ones-row dot = sum(q~)
                qnT += g_qn[q][rb][r];
            }
            // d2 = qn + (ssq + 2 eps ssm) + D eps^2 - 2 dot - 2 eps qsum
            const float base = qnT - 2.f * EPSV * qsT + (float)D * (EPSV * EPSV);
            #pragma unroll
            for (int w = 0; w < NWAY; ++w) {
                float sum = 0.f;
                #pragma unroll
                for (int k = 0; k < KSHOT; ++k) {
                    const int s = w * KSHOT + k;
                    const float d2 = base + s_sn[s] - 2.f * dt[s];
                    sum += sqrtf(fmaxf(d2, 0.f));
                }
                out[(size_t)(rb * MROWS + r) * NWAY + w] = -sum;
            }
        }
        if (tid == 0) g_ctr[rb] = 0;   // reset for next replay
    }
}

// ---------------------------------------------------------------------------
extern "C" void kernel_launch(void* const* d_in, const int* in_sizes, int n_in,
                              void* d_out, int out_size) {
    const float* support = (const float*)d_in[0];
    const float* query   = (const float*)d_in[1];
    if (n_in >= 2 && in_sizes[0] > in_sizes[1]) {
        const float* t = support; support = query; query = t;
    }
    float* out = (float*)d_out;

    pd_mma<<<dim3(NRB, NSPLIT), THREADS>>>(support, query, out);
}